// round 2
// baseline (speedup 1.0000x reference)
#include <cuda_runtime.h>
#include <cstdint>

#define BB 256
#define PP 196
#define DD 512
#define AA 512
#define MM (BB*PP)   // 50176

// scratch (allocation-free rule: __device__ globals)
__device__ float g_hidden[BB*AA];   // hidden + bv, per (b,a)
__device__ float g_z[BB*PP];        // attention logits
__device__ float g_satt[BB];        // sentinel logit

__device__ __forceinline__ float tanh_fast(float x) {
    // tanh(x) = 1 - 2/(exp(2x)+1); robust at +-inf, ~1e-6 rel err with __expf
    float e = __expf(2.0f * x);
    return 1.0f - 2.0f / (e + 1.0f);
}

// ---------------------------------------------------------------------------
// K1: hidden[b,a] = dh[b,:]@Wh[:,a] + bh[a]   (stored with +bv[a] folded in)
//     s_att[b]   = sum_a tanh(st[b,:]@Ws[:,a] + bs[a] + hidden[b,a]) * Was[a] + bas
// grid 32 blocks x 256 threads, 8 batches per block, 2 a-columns per thread
// ---------------------------------------------------------------------------
__global__ void __launch_bounds__(256) k_prep(
    const float* __restrict__ dh, const float* __restrict__ st,
    const float* __restrict__ Wh, const float* __restrict__ bh,
    const float* __restrict__ Ws, const float* __restrict__ bs,
    const float* __restrict__ Was, const float* __restrict__ bas,
    const float* __restrict__ bv)
{
    __shared__ float dh_s[8*DD];
    __shared__ float st_s[8*DD];
    __shared__ float s_part[8];
    const int tid = threadIdx.x;
    const int b0  = blockIdx.x * 8;

    for (int i = tid; i < 8*DD; i += 256) {
        int b = i >> 9, d = i & 511;
        dh_s[i] = dh[(b0 + b)*DD + d];
        st_s[i] = st[(b0 + b)*DD + d];
    }
    if (tid < 8) s_part[tid] = 0.f;
    __syncthreads();

    for (int aa = 0; aa < 2; ++aa) {
        const int a = tid + aa*256;
        float acch[8], accs[8];
        const float bha = bh[a], bsa = bs[a];
        #pragma unroll
        for (int b = 0; b < 8; ++b) { acch[b] = bha; accs[b] = bsa; }

        #pragma unroll 4
        for (int d = 0; d < DD; ++d) {
            const float wh = Wh[d*AA + a];
            const float ws = Ws[d*AA + a];
            #pragma unroll
            for (int b = 0; b < 8; ++b) {
                acch[b] += dh_s[b*DD + d] * wh;
                accs[b] += st_s[b*DD + d] * ws;
            }
        }
        const float was = Was[a], bva = bv[a];
        #pragma unroll
        for (int b = 0; b < 8; ++b) {
            const float h = acch[b];
            g_hidden[(size_t)(b0 + b)*AA + a] = h + bva;
            float t = tanh_fast(accs[b] + h) * was;
            #pragma unroll
            for (int off = 16; off; off >>= 1)
                t += __shfl_xor_sync(0xffffffffu, t, off);
            if ((tid & 31) == 0) atomicAdd(&s_part[b], t);
        }
    }
    __syncthreads();
    if (tid < 8) g_satt[b0 + tid] = s_part[tid] + bas[0];
}

// ---------------------------------------------------------------------------
// K2: fused  z[m] = bav + sum_a Wav[a] * tanh( enc[m,:]@Wv[:,a] + hidden[b(m),a] )
// 64 M-rows per block, N looped in 8 tiles of 64, K staged in 16-chunks.
// 256 threads, 4x4 microtile (tx = n-group 0..15, ty = m-group 0..15).
// ---------------------------------------------------------------------------
__global__ void __launch_bounds__(256) k_zgemm(
    const float* __restrict__ enc, const float* __restrict__ Wv,
    const float* __restrict__ Wav, const float* __restrict__ bav)
{
    __shared__ __align__(16) float A_s[16*68];   // [k][r], padded row stride 68
    __shared__ __align__(16) float B_s[16*64];   // [k][n]
    __shared__ __align__(16) float wav_s[AA];
    __shared__ float zs[64];

    const int tid = threadIdx.x;
    const int m0  = blockIdx.x * 64;
    const int tx  = tid & 15;    // n-group
    const int ty  = tid >> 4;    // m-group

    for (int i = tid; i < AA; i += 256) wav_s[i] = Wav[i];
    if (tid < 64) zs[tid] = 0.f;

    for (int nt = 0; nt < 8; ++nt) {
        const int n0 = nt * 64;
        float acc[4][4];
        #pragma unroll
        for (int r = 0; r < 4; ++r)
            #pragma unroll
            for (int c = 0; c < 4; ++c) acc[r][c] = 0.f;

        float pa[4], pb[4];
        #pragma unroll
        for (int j = 0; j < 4; ++j) {       // prefetch kb=0
            const int i = tid + 256*j;
            pa[j] = enc[(size_t)(m0 + (i >> 4))*DD + (i & 15)];
            pb[j] = Wv[(size_t)(i >> 6)*AA + n0 + (i & 63)];
        }

        for (int kb = 0; kb < DD; kb += 16) {
            __syncthreads();                 // previous stage consumed / zs init
            #pragma unroll
            for (int j = 0; j < 4; ++j) {
                const int i = tid + 256*j;
                A_s[(i & 15)*68 + (i >> 4)] = pa[j];
                B_s[i] = pb[j];
            }
            __syncthreads();
            if (kb + 16 < DD) {
                #pragma unroll
                for (int j = 0; j < 4; ++j) {
                    const int i = tid + 256*j;
                    pa[j] = enc[(size_t)(m0 + (i >> 4))*DD + kb + 16 + (i & 15)];
                    pb[j] = Wv[(size_t)(kb + 16 + (i >> 6))*AA + n0 + (i & 63)];
                }
            }
            #pragma unroll
            for (int kk = 0; kk < 16; ++kk) {
                const float4 a4 = *reinterpret_cast<const float4*>(&A_s[kk*68 + 4*ty]);
                const float4 b4 = *reinterpret_cast<const float4*>(&B_s[kk*64 + 4*tx]);
                const float av[4] = {a4.x, a4.y, a4.z, a4.w};
                const float bw[4] = {b4.x, b4.y, b4.z, b4.w};
                #pragma unroll
                for (int r = 0; r < 4; ++r)
                    #pragma unroll
                    for (int c = 0; c < 4; ++c)
                        acc[r][c] += av[r] * bw[c];
            }
        }

        // epilogue: tanh(v + hidden) * Wav, reduce over the 64 n's of this tile
        float rsum[4];
        #pragma unroll
        for (int r = 0; r < 4; ++r) {
            const int m = m0 + 4*ty + r;
            const int b = m / PP;
            const float4 h4 = *reinterpret_cast<const float4*>(
                &g_hidden[(size_t)b*AA + n0 + 4*tx]);
            const float hv[4] = {h4.x, h4.y, h4.z, h4.w};
            float s = 0.f;
            #pragma unroll
            for (int c = 0; c < 4; ++c)
                s += tanh_fast(acc[r][c] + hv[c]) * wav_s[n0 + 4*tx + c];
            rsum[r] = s;
        }
        #pragma unroll
        for (int off = 8; off; off >>= 1)
            #pragma unroll
            for (int r = 0; r < 4; ++r)
                rsum[r] += __shfl_xor_sync(0xffffffffu, rsum[r], off);
        if (tx == 0) {
            #pragma unroll
            for (int r = 0; r < 4; ++r) zs[4*ty + r] += rsum[r];   // unique owner
        }
    }
    __syncthreads();
    if (tid < 64) g_z[m0 + tid] = zs[tid] + bav[0];
}

// ---------------------------------------------------------------------------
// K3: softmax(z) -> alpha ; extended softmax with s_att -> beta ;
//     c_t = enc^T alpha ; c_hat = beta*st + (1-beta)*c_t
// grid (B, 2): each block owns 256 of the 512 d's of batch b.
// ---------------------------------------------------------------------------
__global__ void __launch_bounds__(256) k_soft(
    const float* __restrict__ enc, const float* __restrict__ st,
    float* __restrict__ out)
{
    __shared__ float zsh[PP];
    __shared__ float alpha_sh[PP];
    __shared__ float red[256];
    const int tid = threadIdx.x;
    const int b   = blockIdx.x;
    const int y   = blockIdx.y;

    if (tid < PP) zsh[tid] = g_z[b*PP + tid];
    __syncthreads();

    // max over 196
    red[tid] = (tid < PP) ? zsh[tid] : -1e30f;
    __syncthreads();
    for (int s = 128; s > 0; s >>= 1) {
        if (tid < s) red[tid] = fmaxf(red[tid], red[tid + s]);
        __syncthreads();
    }
    const float m1 = red[0];
    __syncthreads();

    // sum exp
    const float e = (tid < PP) ? __expf(zsh[tid] - m1) : 0.f;
    red[tid] = e;
    __syncthreads();
    for (int s = 128; s > 0; s >>= 1) {
        if (tid < s) red[tid] += red[tid + s];
        __syncthreads();
    }
    const float sum1 = red[0];

    if (tid < PP) {
        const float alpha = e / sum1;
        alpha_sh[tid] = alpha;
        if (y == 0) out[BB*DD + b*PP + tid] = alpha;   // alpha_t
    }

    const float sa   = g_satt[b];
    const float m2   = fmaxf(m1, sa);
    const float sum2 = sum1 * __expf(m1 - m2) + __expf(sa - m2);
    const float beta = __expf(sa - m2) / sum2;
    if (y == 0 && tid == 0) out[BB*DD + BB*PP + b] = beta;  // beta_t
    __syncthreads();

    // c_t for this thread's d
    const int d = y*256 + tid;
    const float* ep = enc + (size_t)b*PP*DD + d;
    float acc = 0.f;
    #pragma unroll 4
    for (int p = 0; p < PP; ++p)
        acc += ep[(size_t)p*DD] * alpha_sh[p];

    out[b*DD + d] = beta * st[b*DD + d] + (1.f - beta) * acc;  // c_hat_t
}

// ---------------------------------------------------------------------------
extern "C" void kernel_launch(void* const* d_in, const int* in_sizes, int n_in,
                              void* d_out, int out_size) {
    const float* enc = (const float*)d_in[0];
    const float* dh  = (const float*)d_in[1];
    const float* st  = (const float*)d_in[2];
    const float* Wv  = (const float*)d_in[3];
    const float* bv  = (const float*)d_in[4];
    const float* Wh  = (const float*)d_in[5];
    const float* bh  = (const float*)d_in[6];
    const float* Ws  = (const float*)d_in[7];
    const float* bs  = (const float*)d_in[8];
    const float* Wav = (const float*)d_in[9];
    const float* bav = (const float*)d_in[10];
    const float* Was = (const float*)d_in[11];
    const float* bas = (const float*)d_in[12];
    float* out = (float*)d_out;

    k_prep <<<32, 256>>>(dh, st, Wh, bh, Ws, bs, Was, bas, bv);
    k_zgemm<<<MM/64, 256>>>(enc, Wv, Wav, bav);
    k_soft <<<dim3(BB, 2), 256>>>(enc, st, out);
}

// round 3
// speedup vs baseline: 1.7557x; 1.7557x over previous
#include <cuda_runtime.h>
#include <cstdint>

#define BB 256
#define PP 196
#define DD 512
#define AA 512
#define MM (BB*PP)   // 50176

// scratch (allocation-free rule: __device__ globals)
__device__ float g_hidden[BB*AA];   // hidden + bv  (for K2 epilogue)
__device__ float g_sh[BB*AA];       // st@Ws + bs + hidden (pre-tanh, for s_att)
__device__ float g_z[BB*PP];        // attention logits

__device__ __forceinline__ float tanh_fast(float x) {
    float e = __expf(2.0f * x);
    return 1.0f - 2.0f / (e + 1.0f);
}

__device__ __forceinline__ uint32_t f2tf(float x) {
    uint32_t r;
    asm("cvt.rna.tf32.f32 %0, %1;" : "=r"(r) : "f"(x));
    return r;
}

__device__ __forceinline__ void mma8(float* c, const uint32_t* a, const uint32_t* b) {
    asm volatile(
        "mma.sync.aligned.m16n8k8.row.col.f32.tf32.tf32.f32 "
        "{%0,%1,%2,%3}, {%4,%5,%6,%7}, {%8,%9}, {%0,%1,%2,%3};"
        : "+f"(c[0]), "+f"(c[1]), "+f"(c[2]), "+f"(c[3])
        : "r"(a[0]), "r"(a[1]), "r"(a[2]), "r"(a[3]), "r"(b[0]), "r"(b[1]));
}

// ---------------------------------------------------------------------------
// K1: hidden = dh@Wh + bh (stored +bv);  g_sh = st@Ws + bs + hidden (pre-tanh)
// Tiled GEMM: grid (4 a-tiles, 16 b-tiles), 256 thr, tile 16b x 128a, BK=32.
// Thread = 4 batches x 2 a-cols.
// ---------------------------------------------------------------------------
__global__ void __launch_bounds__(256) k_prep(
    const float* __restrict__ dh, const float* __restrict__ st,
    const float* __restrict__ Wh, const float* __restrict__ bh,
    const float* __restrict__ Ws, const float* __restrict__ bs,
    const float* __restrict__ bv)
{
    __shared__ float dh_s[16][33], st_s[16][33];
    __shared__ float Wh_s[32][128], Ws_s[32][128];
    const int tid = threadIdx.x;
    const int b0  = blockIdx.y * 16;
    const int a0  = blockIdx.x * 128;
    const int al  = (tid & 63) * 2;
    const int bl  = (tid >> 6) * 4;

    float acch[4][2] = {}, accs[4][2] = {};

    for (int kb = 0; kb < DD; kb += 32) {
        __syncthreads();
        #pragma unroll
        for (int j = 0; j < 2; ++j) {
            const int i  = tid + j*256;          // 0..511
            const int bb = i >> 5, kk = i & 31;
            dh_s[bb][kk] = dh[(b0 + bb)*DD + kb + kk];
            st_s[bb][kk] = st[(b0 + bb)*DD + kb + kk];
        }
        #pragma unroll
        for (int j = 0; j < 4; ++j) {
            const int i  = tid + j*256;          // f4 idx 0..1023
            const int kk = i >> 5, nq = i & 31;
            *(float4*)&Wh_s[kk][nq*4] = *(const float4*)&Wh[(size_t)(kb+kk)*AA + a0 + nq*4];
            *(float4*)&Ws_s[kk][nq*4] = *(const float4*)&Ws[(size_t)(kb+kk)*AA + a0 + nq*4];
        }
        __syncthreads();
        #pragma unroll 8
        for (int k = 0; k < 32; ++k) {
            const float2 wh = *(const float2*)&Wh_s[k][al];
            const float2 ws = *(const float2*)&Ws_s[k][al];
            #pragma unroll
            for (int bi = 0; bi < 4; ++bi) {
                const float dv = dh_s[bl+bi][k], sv = st_s[bl+bi][k];
                acch[bi][0] += dv*wh.x;  acch[bi][1] += dv*wh.y;
                accs[bi][0] += sv*ws.x;  accs[bi][1] += sv*ws.y;
            }
        }
    }
    #pragma unroll
    for (int bi = 0; bi < 4; ++bi)
        #pragma unroll
        for (int j = 0; j < 2; ++j) {
            const int b = b0 + bl + bi, a = a0 + al + j;
            const float h = acch[bi][j] + bh[a];
            g_hidden[(size_t)b*AA + a] = h + bv[a];
            g_sh[(size_t)b*AA + a]     = accs[bi][j] + bs[a] + h;
        }
}

// ---------------------------------------------------------------------------
// K2: z[m] = bav + sum_a Wav[a] * tanh( enc[m,:]@Wv[:,a] + hidden[b(m),a] )
// tf32 mma.sync (3x split for fp32 precision). Block tile 128x128, BK=32,
// 8 warps (4m x 2n), warp tile 32x64. N looped over 4 tiles per block.
// ---------------------------------------------------------------------------
#define BM 128
#define BN 128
#define BK 32

__global__ void __launch_bounds__(256) k_zgemm(
    const float* __restrict__ enc, const float* __restrict__ Wv,
    const float* __restrict__ Wav, const float* __restrict__ bav)
{
    __shared__ float A_s[BM][36];     // [row][k], banks 4r+k conflict-free
    __shared__ float B_s[BK][136];    // [k][n],  banks 8k+n conflict-free
    __shared__ float wav_s[BN];
    __shared__ float h_s[2][BN];
    __shared__ float zs[BM];

    const int tid  = threadIdx.x, lane = tid & 31, wid = tid >> 5;
    const int wm   = wid & 3;          // m-warp 0..3
    const int wn   = wid >> 2;         // n-warp 0..1
    const int gid  = lane >> 2, tig = lane & 3;
    const int m0   = blockIdx.x * BM;
    const int b0   = m0 / PP;
    const int b1   = (m0 + BM - 1) / PP;
    const int bsplit = (b0 + 1) * PP;  // rows >= bsplit belong to b1

    if (tid < BM) zs[tid] = 0.f;

    for (int nt = 0; nt < 4; ++nt) {
        const int n0 = nt * BN;
        __syncthreads();  // protect h_s/wav_s from previous epilogue readers
        for (int i = tid; i < BN; i += 256) {
            wav_s[i]  = Wav[n0 + i];
            h_s[0][i] = g_hidden[(size_t)b0*AA + n0 + i];
            h_s[1][i] = g_hidden[(size_t)b1*AA + n0 + i];
        }

        float acc[2][8][4];
        #pragma unroll
        for (int mi = 0; mi < 2; ++mi)
            #pragma unroll
            for (int ni = 0; ni < 8; ++ni)
                #pragma unroll
                for (int q = 0; q < 4; ++q) acc[mi][ni][q] = 0.f;

        // prefetch stage kb=0 into registers
        float4 pa[4], pb[4];
        #pragma unroll
        for (int j = 0; j < 4; ++j) {
            const int ia = tid + j*256;               // 0..1023
            pa[j] = *(const float4*)&enc[(size_t)(m0 + (ia>>3))*DD + (ia&7)*4];
            pb[j] = *(const float4*)&Wv[(size_t)(ia>>5)*AA + n0 + (ia&31)*4];
        }

        for (int kb = 0; kb < DD; kb += BK) {
            __syncthreads();
            #pragma unroll
            for (int j = 0; j < 4; ++j) {
                const int ia = tid + j*256;
                *(float4*)&A_s[ia>>3][(ia&7)*4]  = pa[j];
                *(float4*)&B_s[ia>>5][(ia&31)*4] = pb[j];
            }
            __syncthreads();
            if (kb + BK < DD) {
                #pragma unroll
                for (int j = 0; j < 4; ++j) {
                    const int ia = tid + j*256;
                    pa[j] = *(const float4*)&enc[(size_t)(m0 + (ia>>3))*DD + kb + BK + (ia&7)*4];
                    pb[j] = *(const float4*)&Wv[(size_t)(kb + BK + (ia>>5))*AA + n0 + (ia&31)*4];
                }
            }
            #pragma unroll
            for (int k8 = 0; k8 < 4; ++k8) {
                const int kk = k8 * 8;
                uint32_t ah[2][4], al_[2][4], bh_[8][2], bl_[8][2];
                #pragma unroll
                for (int mi = 0; mi < 2; ++mi) {
                    const int r = wm*32 + mi*16 + gid;
                    float af[4];
                    af[0] = A_s[r  ][kk + tig];
                    af[1] = A_s[r+8][kk + tig];
                    af[2] = A_s[r  ][kk + tig + 4];
                    af[3] = A_s[r+8][kk + tig + 4];
                    #pragma unroll
                    for (int q = 0; q < 4; ++q) {
                        ah[mi][q]  = f2tf(af[q]);
                        al_[mi][q] = f2tf(af[q] - __uint_as_float(ah[mi][q]));
                    }
                }
                #pragma unroll
                for (int ni = 0; ni < 8; ++ni) {
                    const int n = wn*64 + ni*8 + gid;
                    float bf[2];
                    bf[0] = B_s[kk + tig    ][n];
                    bf[1] = B_s[kk + tig + 4][n];
                    #pragma unroll
                    for (int q = 0; q < 2; ++q) {
                        bh_[ni][q] = f2tf(bf[q]);
                        bl_[ni][q] = f2tf(bf[q] - __uint_as_float(bh_[ni][q]));
                    }
                }
                #pragma unroll
                for (int mi = 0; mi < 2; ++mi)
                    #pragma unroll
                    for (int ni = 0; ni < 8; ++ni) {
                        mma8(acc[mi][ni], ah[mi],  bh_[ni]);
                        mma8(acc[mi][ni], ah[mi],  bl_[ni]);
                        mma8(acc[mi][ni], al_[mi], bh_[ni]);
                    }
            }
        }

        // epilogue: tanh(v + hidden) * Wav, per-row partial sums
        float rs[2][2] = {0.f, 0.f, 0.f, 0.f};
        #pragma unroll
        for (int mi = 0; mi < 2; ++mi) {
            const int r_lo = m0 + wm*32 + mi*16 + gid;
            const int s_lo = (r_lo     >= bsplit) ? 1 : 0;
            const int s_hi = (r_lo + 8 >= bsplit) ? 1 : 0;
            #pragma unroll
            for (int ni = 0; ni < 8; ++ni) {
                const int c0 = wn*64 + ni*8 + 2*tig;
                const float w0 = wav_s[c0], w1 = wav_s[c0+1];
                rs[mi][0] += tanh_fast(acc[mi][ni][0] + h_s[s_lo][c0  ]) * w0
                           + tanh_fast(acc[mi][ni][1] + h_s[s_lo][c0+1]) * w1;
                rs[mi][1] += tanh_fast(acc[mi][ni][2] + h_s[s_hi][c0  ]) * w0
                           + tanh_fast(acc[mi][ni][3] + h_s[s_hi][c0+1]) * w1;
            }
        }
        #pragma unroll
        for (int off = 1; off <= 2; off <<= 1) {
            #pragma unroll
            for (int mi = 0; mi < 2; ++mi) {
                rs[mi][0] += __shfl_xor_sync(0xffffffffu, rs[mi][0], off);
                rs[mi][1] += __shfl_xor_sync(0xffffffffu, rs[mi][1], off);
            }
        }
        if (tig == 0) {
            #pragma unroll
            for (int mi = 0; mi < 2; ++mi) {
                atomicAdd(&zs[wm*32 + mi*16 + gid    ], rs[mi][0]);
                atomicAdd(&zs[wm*32 + mi*16 + gid + 8], rs[mi][1]);
            }
        }
    }
    __syncthreads();
    if (tid < BM) g_z[m0 + tid] = zs[tid] + bav[0];
}

// ---------------------------------------------------------------------------
// K3: s_att reduce; softmax(z) -> alpha; extended softmax -> beta;
//     c_t = enc^T alpha; c_hat = beta*st + (1-beta)*c_t
// grid (B, 2): each block owns 256 of the 512 d's of batch b.
// ---------------------------------------------------------------------------
__global__ void __launch_bounds__(256) k_soft(
    const float* __restrict__ enc, const float* __restrict__ st,
    const float* __restrict__ Was, const float* __restrict__ bas,
    float* __restrict__ out)
{
    __shared__ float zsh[PP];
    __shared__ float alpha_sh[PP];
    __shared__ float red[256];
    const int tid = threadIdx.x;
    const int b   = blockIdx.x;
    const int y   = blockIdx.y;

    // s_att[b] = sum_a tanh(g_sh[b,a]) * Was[a] + bas
    float sacc = 0.f;
    for (int i = tid; i < AA; i += 256)
        sacc += tanh_fast(g_sh[(size_t)b*AA + i]) * Was[i];
    red[tid] = sacc;
    __syncthreads();
    for (int s = 128; s > 0; s >>= 1) {
        if (tid < s) red[tid] += red[tid + s];
        __syncthreads();
    }
    const float sa = red[0] + bas[0];
    __syncthreads();

    if (tid < PP) zsh[tid] = g_z[b*PP + tid];
    __syncthreads();

    red[tid] = (tid < PP) ? zsh[tid] : -1e30f;
    __syncthreads();
    for (int s = 128; s > 0; s >>= 1) {
        if (tid < s) red[tid] = fmaxf(red[tid], red[tid + s]);
        __syncthreads();
    }
    const float m1 = red[0];
    __syncthreads();

    const float e = (tid < PP) ? __expf(zsh[tid] - m1) : 0.f;
    red[tid] = e;
    __syncthreads();
    for (int s = 128; s > 0; s >>= 1) {
        if (tid < s) red[tid] += red[tid + s];
        __syncthreads();
    }
    const float sum1 = red[0];

    if (tid < PP) {
        const float alpha = e / sum1;
        alpha_sh[tid] = alpha;
        if (y == 0) out[BB*DD + b*PP + tid] = alpha;     // alpha_t
    }

    const float m2   = fmaxf(m1, sa);
    const float sum2 = sum1 * __expf(m1 - m2) + __expf(sa - m2);
    const float beta = __expf(sa - m2) / sum2;
    if (y == 0 && tid == 0) out[BB*DD + BB*PP + b] = beta;  // beta_t
    __syncthreads();

    const int d = y*256 + tid;
    const float* ep = enc + (size_t)b*PP*DD + d;
    float acc = 0.f;
    #pragma unroll 8
    for (int p = 0; p < PP; ++p)
        acc += ep[(size_t)p*DD] * alpha_sh[p];

    out[b*DD + d] = beta * st[b*DD + d] + (1.f - beta) * acc;  // c_hat_t
}

// ---------------------------------------------------------------------------
extern "C" void kernel_launch(void* const* d_in, const int* in_sizes, int n_in,
                              void* d_out, int out_size) {
    const float* enc = (const float*)d_in[0];
    const float* dh  = (const float*)d_in[1];
    const float* st  = (const float*)d_in[2];
    const float* Wv  = (const float*)d_in[3];
    const float* bv  = (const float*)d_in[4];
    const float* Wh  = (const float*)d_in[5];
    const float* bh  = (const float*)d_in[6];
    const float* Ws  = (const float*)d_in[7];
    const float* bs  = (const float*)d_in[8];
    const float* Wav = (const float*)d_in[9];
    const float* bav = (const float*)d_in[10];
    const float* Was = (const float*)d_in[11];
    const float* bas = (const float*)d_in[12];
    float* out = (float*)d_out;

    k_prep <<<dim3(4, 16), 256>>>(dh, st, Wh, bh, Ws, bs, bv);
    k_zgemm<<<MM/BM, 256>>>(enc, Wv, Wav, bav);
    k_soft <<<dim3(BB, 2), 256>>>(enc, st, Was, bas, out);
}